// round 16
// baseline (speedup 1.0000x reference)
#include <cuda_runtime.h>
#include <cuda_bf16.h>
#include <cstdint>

// Problem constants (fixed shapes from reference setup_inputs)
#define N 384
#define D 512
#define MARGIN 1.0f
#define KSLICES 4
#define KS (D / KSLICES)          // 128 k per slice (2 chunks of 64)
#define TILES 6                   // 6x6 tiles of 64x64
#define LDT 68                    // smem tile row stride: 4 mod 32 -> conflict-free frags
#define APB 4                     // anchors per phase-2 block
#define NBLK2 (N / APB)           // 96 phase-2 blocks

// Scratch: device globals (no allocation allowed)
__device__ float g_Gp[KSLICES][N * N];  // split-K Gram partials (tf32 mma, fp32 accum)
__device__ float g_sq[N];               // fp32 row sums of x*x
__device__ float g_asum[N];             // per-anchor triplet loss sum
__device__ int   g_acnt[N];             // per-anchor valid-triple count
__device__ unsigned g_ticket = 0;       // finalize ticket (self-resetting)

// Round-to-nearest TF32 (matches cuBLAS; fp32-vs-tf32 loss delta ~1e-5, safe)
__device__ __forceinline__ uint32_t f2tf(float x) {
    uint32_t u;
    asm("cvt.rna.tf32.f32 %0, %1;" : "=r"(u) : "f"(x));
    return u;
}

__device__ __forceinline__ void mma_tf32(float c[4],
                                         uint32_t a0, uint32_t a1, uint32_t a2, uint32_t a3,
                                         uint32_t b0, uint32_t b1) {
    asm volatile(
        "mma.sync.aligned.m16n8k8.row.col.f32.tf32.tf32.f32 "
        "{%0,%1,%2,%3}, {%4,%5,%6,%7}, {%8,%9}, {%0,%1,%2,%3};"
        : "+f"(c[0]), "+f"(c[1]), "+f"(c[2]), "+f"(c[3])
        : "r"(a0), "r"(a1), "r"(a2), "r"(a3), "r"(b0), "r"(b1));
}

// ---------------------------------------------------------------------------
// Kernel A: blocks 0..143 split-K Gram (KS=128, register double-buffered);
// blocks 144..239 g_sq (4 rows per block).
// ---------------------------------------------------------------------------
__global__ void __launch_bounds__(256)
gram_sq_kernel(const float* __restrict__ X) {
    __shared__ float pool[2 * 64 * LDT];   // 34816 B
    const int b   = blockIdx.x;
    const int tid = threadIdx.x;

    if (b < KSLICES * 36) {
        uint32_t* As = (uint32_t*)pool;             // [64][LDT] tf32 bits
        uint32_t* Bs = (uint32_t*)pool + 64 * LDT;
        const int kslice = b / 36;
        const int t      = b % 36;
        const int row0 = (t / TILES) * 64;
        const int col0 = (t % TILES) * 64;
        const int kbase = kslice * KS;

        const int lr = tid >> 3;          // 0..31
        const int kg = tid & 7;           // 0..7

        // prefetch chunk 0 (8 independent float4 LDG)
        float4 pva[2][2], pvb[2][2];
#pragma unroll
        for (int rh = 0; rh < 2; rh++) {
            const int r = lr + rh * 32;
#pragma unroll
            for (int h = 0; h < 2; h++) {
                const int kcol = kg * 4 + h * 32;
                pva[rh][h] = *(const float4*)&X[(row0 + r) * D + kbase + kcol];
                pvb[rh][h] = *(const float4*)&X[(col0 + r) * D + kbase + kcol];
            }
        }

        const int warp = tid >> 5;
        const int lane = tid & 31;
        const int wm = warp >> 1;         // 0..3
        const int wn = warp & 1;          // 0..1
        const int g  = lane >> 2;         // 0..7
        const int tg = lane & 3;          // 0..3

        float c[4][4];
#pragma unroll
        for (int nf = 0; nf < 4; nf++)
#pragma unroll
            for (int i = 0; i < 4; i++) c[nf][i] = 0.f;

        const uint32_t* Ar0 = As + (wm * 16 + g) * LDT;
        const uint32_t* Ar1 = As + (wm * 16 + g + 8) * LDT;
        const uint32_t* Bq0 = Bs + (wn * 32 + g) * LDT;

#pragma unroll
        for (int ch = 0; ch < 2; ch++) {              // 2 chunks of 64 k
#pragma unroll
            for (int rh = 0; rh < 2; rh++) {
                const int r = lr + rh * 32;
#pragma unroll
                for (int h = 0; h < 2; h++) {
                    const int kcol = kg * 4 + h * 32;
                    float4 va = pva[rh][h], vb = pvb[rh][h];
                    *(uint4*)&As[r * LDT + kcol] =
                        make_uint4(f2tf(va.x), f2tf(va.y), f2tf(va.z), f2tf(va.w));
                    *(uint4*)&Bs[r * LDT + kcol] =
                        make_uint4(f2tf(vb.x), f2tf(vb.y), f2tf(vb.z), f2tf(vb.w));
                }
            }
            __syncthreads();

            if (ch == 0) {                 // prefetch next chunk during mma
                const int kb1 = kbase + 64;
#pragma unroll
                for (int rh = 0; rh < 2; rh++) {
                    const int r = lr + rh * 32;
#pragma unroll
                    for (int h = 0; h < 2; h++) {
                        const int kcol = kg * 4 + h * 32;
                        pva[rh][h] = *(const float4*)&X[(row0 + r) * D + kb1 + kcol];
                        pvb[rh][h] = *(const float4*)&X[(col0 + r) * D + kb1 + kcol];
                    }
                }
            }

#pragma unroll
            for (int ks = 0; ks < 8; ks++) {
                const int k0 = ks * 8;
                uint32_t a0 = Ar0[k0 + tg];
                uint32_t a1 = Ar1[k0 + tg];
                uint32_t a2 = Ar0[k0 + tg + 4];
                uint32_t a3 = Ar1[k0 + tg + 4];
#pragma unroll
                for (int nf = 0; nf < 4; nf++) {
                    const uint32_t* Bq = Bq0 + nf * 8 * LDT;
                    uint32_t b0 = Bq[k0 + tg];
                    uint32_t b1 = Bq[k0 + tg + 4];
                    mma_tf32(c[nf], a0, a1, a2, a3, b0, b1);
                }
            }
            if (ch == 0) __syncthreads();
        }

        float* Gp = g_Gp[kslice];
#pragma unroll
        for (int nf = 0; nf < 4; nf++) {
            const int ccol = col0 + wn * 32 + nf * 8 + 2 * tg;
            *(float2*)&Gp[(row0 + wm * 16 + g)     * N + ccol] = make_float2(c[nf][0], c[nf][1]);
            *(float2*)&Gp[(row0 + wm * 16 + g + 8) * N + ccol] = make_float2(c[nf][2], c[nf][3]);
        }
    } else {
        // Squared row norms: 4 rows per block, 64 threads each (fp32, fixed order)
        const int quad = tid >> 6;                 // 0..3
        const int lane = tid & 63;
        const int row  = (b - KSLICES * 36) * 4 + quad;
        const float* xr = X + row * D;
        float s = 0.0f;
#pragma unroll
        for (int i = 0; i < D / 64; i++) {
            float v = xr[lane + i * 64];
            s = fmaf(v, v, s);
        }
        float* red = pool + quad * 64;
        red[lane] = s;
        __syncthreads();
#pragma unroll
        for (int st = 32; st > 0; st >>= 1) {
            if (lane < st) red[lane] += red[lane + st];
            __syncthreads();
        }
        if (lane == 0) g_sq[row] = red[0];
    }
}

// ---------------------------------------------------------------------------
// Kernel B: 96 blocks, APB=4 anchors per block.
//  - labels staged once; 4 distance rows (deep-MLP LDG of split-K partials)
//  - warps 0..3 compact their own anchor IN PARALLEL (deterministic ballots)
//  - hinge pair sums per anchor across all 256 threads; shuffle reduce
//  - ticketed finalize (last of 96): fixed-order reduce -> out[0]
// ---------------------------------------------------------------------------
__global__ void __launch_bounds__(256)
triplet_kernel(const int* __restrict__ labels, float* __restrict__ out) {
    __shared__ int   lab[N];
    __shared__ float dr[APB][N];
    __shared__ float pd[APB][N];
    __shared__ float nd[APB][N];
    __shared__ float red[APB][8];
    __shared__ int   s_np[APB], s_nn[APB], s_last;

    const int b    = blockIdx.x;
    const int tid  = threadIdx.x;
    const int warp = tid >> 5;
    const int lane = tid & 31;
    const int a0   = b * APB;

    // stage labels
    for (int j = tid; j < N; j += 256) lab[j] = labels[j];

    // 4 distance rows: fixed-order split-K combine, safe sqrt
#pragma unroll
    for (int aa = 0; aa < APB; aa++) {
        const int a = a0 + aa;
        const float sqa = g_sq[a];
        for (int j = tid; j < N; j += 256) {
            float g = (g_Gp[0][a * N + j] + g_Gp[1][a * N + j])
                    + (g_Gp[2][a * N + j] + g_Gp[3][a * N + j]);
            float d2 = sqa + g_sq[j] - 2.0f * g;
            dr[aa][j] = sqrtf(fmaxf(d2, 0.0f));
        }
    }
    __syncthreads();

    // parallel per-warp compaction: warp w (<APB) handles anchor a0+w
    if (warp < APB) {
        const int la = lab[a0 + warp];
        int npos = 0, nneg = 0;
#pragma unroll
        for (int c = 0; c < N / 32; c++) {
            int j = c * 32 + lane;
            bool isp = (lab[j] == la);
            unsigned m = __ballot_sync(0xffffffffu, isp);
            int below = __popc(m & ((1u << lane) - 1u));
            float d = dr[warp][j];
            if (isp) pd[warp][npos + below] = d;
            else     nd[warp][nneg + (lane - below)] = d;
            int p = __popc(m);
            npos += p;
            nneg += 32 - p;
        }
        if (lane == 0) { s_np[warp] = npos; s_nn[warp] = nneg; }
    }
    __syncthreads();

    // hinge pair sums (all 256 threads per anchor, fixed order)
#pragma unroll
    for (int aa = 0; aa < APB; aa++) {
        const int np = s_np[aa];
        const int nn = s_nn[aa];
        float acc = 0.0f;
        for (int p = 0; p < np; p++) {
            const float dpm = pd[aa][p] + MARGIN;
            for (int n = tid; n < nn; n += 256)
                acc += fmaxf(dpm - nd[aa][n], 0.0f);
        }
#pragma unroll
        for (int o = 16; o > 0; o >>= 1)
            acc += __shfl_down_sync(0xffffffffu, acc, o);
        if (lane == 0) red[aa][warp] = acc;
    }
    __syncthreads();

    if (tid < APB) {
        float s = ((red[tid][0] + red[tid][1]) + (red[tid][2] + red[tid][3]))
                + ((red[tid][4] + red[tid][5]) + (red[tid][6] + red[tid][7]));
        g_asum[a0 + tid] = s;
        g_acnt[a0 + tid] = s_np[tid] * s_nn[tid];
    }

    // ---------------- ticketed finalize (last of 96 blocks) ----------------
    __syncthreads();
    if (tid == 0) {
        __threadfence();
        unsigned t = atomicAdd(&g_ticket, 1u);
        s_last = (t == NBLK2 - 1) ? 1 : 0;
    }
    __syncthreads();

    if (s_last) {
        if (tid == 0) g_ticket = 0;      // reset for next replay
        __threadfence();                  // acquire: see all g_asum/g_acnt

        float* rs = (float*)dr;           // reuse smem
        int*   rc = (int*)pd;
        float s = 0.0f;
        int   c = 0;
        for (int i = tid; i < N; i += 256) {  // fixed order -> deterministic
            s += g_asum[i];
            c += g_acnt[i];
        }
        rs[tid] = s;
        rc[tid] = c;
        __syncthreads();
#pragma unroll
        for (int st = 128; st > 0; st >>= 1) {
            if (tid < st) { rs[tid] += rs[tid + st]; rc[tid] += rc[tid + st]; }
            __syncthreads();
        }
        if (tid == 0) {
            out[0] = rs[0] / ((float)rc[0] + 1e-16f);
        }
    }
}

// ---------------------------------------------------------------------------
extern "C" void kernel_launch(void* const* d_in, const int* in_sizes, int n_in,
                              void* d_out, int out_size) {
    const float* X      = (const float*)d_in[0];
    const int*   labels = (const int*)d_in[1];
    float*       out    = (float*)d_out;

    gram_sq_kernel<<<KSLICES * 36 + 96, 256>>>(X);
    triplet_kernel<<<NBLK2, 256>>>(labels, out);
}

// round 17
// speedup vs baseline: 1.9301x; 1.9301x over previous
#include <cuda_runtime.h>
#include <cuda_bf16.h>
#include <cstdint>

// Problem constants (fixed shapes from reference setup_inputs)
#define N 384
#define D 512
#define MARGIN 1.0f
#define KSLICES 4
#define KS (D / KSLICES)          // 128 k per slice (2 chunks of 64)
#define TILES 6                   // 6x6 tiles of 64x64
#define LDT 68                    // smem tile row stride: 4 mod 32 -> conflict-free frags
#define NCHUNK (N / 32)           // 12 label chunks

// Scratch: device globals (no allocation allowed)
__device__ float g_Gp[KSLICES][N * N];  // split-K Gram partials (tf32 mma, fp32 accum)
__device__ float g_sq[N];               // fp32 row sums of x*x
__device__ float g_asum[N];             // per-anchor triplet loss sum
__device__ int   g_acnt[N];             // per-anchor valid-triple count
__device__ unsigned g_ticket = 0;       // finalize ticket (self-resetting)

// Round-to-nearest TF32 (matches cuBLAS; fp32-vs-tf32 loss delta ~1e-5, safe)
__device__ __forceinline__ uint32_t f2tf(float x) {
    uint32_t u;
    asm("cvt.rna.tf32.f32 %0, %1;" : "=r"(u) : "f"(x));
    return u;
}

__device__ __forceinline__ void mma_tf32(float c[4],
                                         uint32_t a0, uint32_t a1, uint32_t a2, uint32_t a3,
                                         uint32_t b0, uint32_t b1) {
    asm volatile(
        "mma.sync.aligned.m16n8k8.row.col.f32.tf32.tf32.f32 "
        "{%0,%1,%2,%3}, {%4,%5,%6,%7}, {%8,%9}, {%0,%1,%2,%3};"
        : "+f"(c[0]), "+f"(c[1]), "+f"(c[2]), "+f"(c[3])
        : "r"(a0), "r"(a1), "r"(a2), "r"(a3), "r"(b0), "r"(b1));
}

// ---------------------------------------------------------------------------
// Kernel A: blocks 0..143 split-K Gram (KS=128, register double-buffered);
// blocks 144..239 g_sq (4 rows per block). Unchanged from R15 (worked).
// ---------------------------------------------------------------------------
__global__ void __launch_bounds__(256)
gram_sq_kernel(const float* __restrict__ X) {
    __shared__ float pool[2 * 64 * LDT];   // 34816 B
    const int b   = blockIdx.x;
    const int tid = threadIdx.x;

    if (b < KSLICES * 36) {
        uint32_t* As = (uint32_t*)pool;             // [64][LDT] tf32 bits
        uint32_t* Bs = (uint32_t*)pool + 64 * LDT;
        const int kslice = b / 36;
        const int t      = b % 36;
        const int row0 = (t / TILES) * 64;
        const int col0 = (t % TILES) * 64;
        const int kbase = kslice * KS;

        const int lr = tid >> 3;          // 0..31
        const int kg = tid & 7;           // 0..7

        float4 pva[2][2], pvb[2][2];
#pragma unroll
        for (int rh = 0; rh < 2; rh++) {
            const int r = lr + rh * 32;
#pragma unroll
            for (int h = 0; h < 2; h++) {
                const int kcol = kg * 4 + h * 32;
                pva[rh][h] = *(const float4*)&X[(row0 + r) * D + kbase + kcol];
                pvb[rh][h] = *(const float4*)&X[(col0 + r) * D + kbase + kcol];
            }
        }

        const int warp = tid >> 5;
        const int lane = tid & 31;
        const int wm = warp >> 1;         // 0..3
        const int wn = warp & 1;          // 0..1
        const int g  = lane >> 2;         // 0..7
        const int tg = lane & 3;          // 0..3

        float c[4][4];
#pragma unroll
        for (int nf = 0; nf < 4; nf++)
#pragma unroll
            for (int i = 0; i < 4; i++) c[nf][i] = 0.f;

        const uint32_t* Ar0 = As + (wm * 16 + g) * LDT;
        const uint32_t* Ar1 = As + (wm * 16 + g + 8) * LDT;
        const uint32_t* Bq0 = Bs + (wn * 32 + g) * LDT;

#pragma unroll
        for (int ch = 0; ch < 2; ch++) {              // 2 chunks of 64 k
#pragma unroll
            for (int rh = 0; rh < 2; rh++) {
                const int r = lr + rh * 32;
#pragma unroll
                for (int h = 0; h < 2; h++) {
                    const int kcol = kg * 4 + h * 32;
                    float4 va = pva[rh][h], vb = pvb[rh][h];
                    *(uint4*)&As[r * LDT + kcol] =
                        make_uint4(f2tf(va.x), f2tf(va.y), f2tf(va.z), f2tf(va.w));
                    *(uint4*)&Bs[r * LDT + kcol] =
                        make_uint4(f2tf(vb.x), f2tf(vb.y), f2tf(vb.z), f2tf(vb.w));
                }
            }
            __syncthreads();

            if (ch == 0) {                 // prefetch next chunk during mma
                const int kb1 = kbase + 64;
#pragma unroll
                for (int rh = 0; rh < 2; rh++) {
                    const int r = lr + rh * 32;
#pragma unroll
                    for (int h = 0; h < 2; h++) {
                        const int kcol = kg * 4 + h * 32;
                        pva[rh][h] = *(const float4*)&X[(row0 + r) * D + kb1 + kcol];
                        pvb[rh][h] = *(const float4*)&X[(col0 + r) * D + kb1 + kcol];
                    }
                }
            }

#pragma unroll
            for (int ks = 0; ks < 8; ks++) {
                const int k0 = ks * 8;
                uint32_t a0 = Ar0[k0 + tg];
                uint32_t a1 = Ar1[k0 + tg];
                uint32_t a2 = Ar0[k0 + tg + 4];
                uint32_t a3 = Ar1[k0 + tg + 4];
#pragma unroll
                for (int nf = 0; nf < 4; nf++) {
                    const uint32_t* Bq = Bq0 + nf * 8 * LDT;
                    uint32_t b0 = Bq[k0 + tg];
                    uint32_t b1 = Bq[k0 + tg + 4];
                    mma_tf32(c[nf], a0, a1, a2, a3, b0, b1);
                }
            }
            if (ch == 0) __syncthreads();
        }

        float* Gp = g_Gp[kslice];
#pragma unroll
        for (int nf = 0; nf < 4; nf++) {
            const int ccol = col0 + wn * 32 + nf * 8 + 2 * tg;
            *(float2*)&Gp[(row0 + wm * 16 + g)     * N + ccol] = make_float2(c[nf][0], c[nf][1]);
            *(float2*)&Gp[(row0 + wm * 16 + g + 8) * N + ccol] = make_float2(c[nf][2], c[nf][3]);
        }
    } else {
        const int quad = tid >> 6;                 // 0..3
        const int lane = tid & 63;
        const int row  = (b - KSLICES * 36) * 4 + quad;
        const float* xr = X + row * D;
        float s = 0.0f;
#pragma unroll
        for (int i = 0; i < D / 64; i++) {
            float v = xr[lane + i * 64];
            s = fmaf(v, v, s);
        }
        float* red = pool + quad * 64;
        red[lane] = s;
        __syncthreads();
#pragma unroll
        for (int st = 32; st > 0; st >>= 1) {
            if (lane < st) red[lane] += red[lane + st];
            __syncthreads();
        }
        if (lane == 0) g_sq[row] = red[0];
    }
}

// ---------------------------------------------------------------------------
// Kernel B: 384 blocks, 1 anchor each — minimized serial critical path.
//  - all global loads issued up front (overlap L2 latency once)
//  - compaction: parallel ballots (all warps) -> masks; parallel scatter
//    with ALU-only popc prefix (serial depth 12 -> 2 chunk-iters)
//  - hinge: p distributed over warps, n over lanes (stride-32, conflict-free),
//    2 accumulators -> short FADD chain
//  - ticketed finalize (last of 384)
// ---------------------------------------------------------------------------
__global__ void __launch_bounds__(256)
triplet_kernel(const int* __restrict__ labels, float* __restrict__ out) {
    __shared__ float dr[N];
    __shared__ float pd[N];
    __shared__ float nd[N];
    __shared__ int   lab[N];
    __shared__ unsigned s_mask[NCHUNK];
    __shared__ float red[8];
    __shared__ int   s_np, s_last;

    const int a    = blockIdx.x;
    const int tid  = threadIdx.x;
    const int warp = tid >> 5;
    const int lane = tid & 31;

    // ---- front-load ALL global reads (independent LDGs, overlap latency) ----
    const float sqa = g_sq[a];
    const int   la  = labels[a];
    // each thread: up to 2 j's (j, j+256 when valid)
    const int j0 = tid;
    const int j1 = tid + 256;            // valid iff j1 < N (tid < 128)
    float g0a = g_Gp[0][a * N + j0], g0b = g_Gp[1][a * N + j0];
    float g0c = g_Gp[2][a * N + j0], g0d = g_Gp[3][a * N + j0];
    float sq0 = g_sq[j0];
    int   lb0 = labels[j0];
    float g1a = 0.f, g1b = 0.f, g1c = 0.f, g1d = 0.f, sq1 = 0.f;
    int   lb1 = 0;
    if (j1 < N) {
        g1a = g_Gp[0][a * N + j1]; g1b = g_Gp[1][a * N + j1];
        g1c = g_Gp[2][a * N + j1]; g1d = g_Gp[3][a * N + j1];
        sq1 = g_sq[j1];
        lb1 = labels[j1];
    }

    // distance row + labels into smem
    {
        float g = (g0a + g0b) + (g0c + g0d);
        float d2 = sqa + sq0 - 2.0f * g;
        dr[j0] = sqrtf(fmaxf(d2, 0.0f));
        lab[j0] = lb0;
        if (j1 < N) {
            float gg = (g1a + g1b) + (g1c + g1d);
            float e2 = sqa + sq1 - 2.0f * gg;
            dr[j1] = sqrtf(fmaxf(e2, 0.0f));
            lab[j1] = lb1;
        }
    }
    __syncthreads();

    // ---- compaction step 1: parallel ballots (warp w -> chunks w, w+8) ----
    for (int c = warp; c < NCHUNK; c += 8) {
        int j = c * 32 + lane;
        unsigned m = __ballot_sync(0xffffffffu, lab[j] == la);
        if (lane == 0) s_mask[c] = m;
    }
    __syncthreads();

    // ---- compaction step 2: parallel scatter with popc prefix ----
    {
        // per-lane copy of all masks (broadcast LDS, cheap)
        unsigned mk[NCHUNK];
#pragma unroll
        for (int c = 0; c < NCHUNK; c++) mk[c] = s_mask[c];

        for (int c = warp; c < NCHUNK; c += 8) {
            int posoff = 0;
            for (int cc = 0; cc < c; cc++) posoff += __popc(mk[cc]);   // ALU only
            int negoff = 32 * c - posoff;
            unsigned m = mk[c];
            int j = c * 32 + lane;
            int below = __popc(m & ((1u << lane) - 1u));
            float d = dr[j];
            if ((m >> lane) & 1u) pd[posoff + below] = d;
            else                  nd[negoff + (lane - below)] = d;
        }
        if (tid == 0) {
            int np = 0;
#pragma unroll
            for (int c = 0; c < NCHUNK; c++) np += __popc(mk[c]);
            s_np = np;
        }
    }
    __syncthreads();

    const int np = s_np;
    const int nn = N - np;

    // ---- hinge: p over warps, n over lanes (stride 32, conflict-free) ----
    float acc0 = 0.0f, acc1 = 0.0f;
    for (int p = warp; p < np; p += 8) {
        const float dpm = pd[p] + MARGIN;       // broadcast LDS
        int n = lane;
        for (; n + 32 < nn; n += 64) {
            acc0 += fmaxf(dpm - nd[n], 0.0f);
            acc1 += fmaxf(dpm - nd[n + 32], 0.0f);
        }
        if (n < nn) acc0 += fmaxf(dpm - nd[n], 0.0f);
    }
    float acc = acc0 + acc1;
#pragma unroll
    for (int o = 16; o > 0; o >>= 1)
        acc += __shfl_down_sync(0xffffffffu, acc, o);
    if (lane == 0) red[warp] = acc;
    __syncthreads();
    if (tid == 0) {
        float s = ((red[0] + red[1]) + (red[2] + red[3]))
                + ((red[4] + red[5]) + (red[6] + red[7]));
        g_asum[a] = s;
        g_acnt[a] = np * nn;
    }

    // ---------------- ticketed finalize (last of 384) ----------------
    __syncthreads();
    if (tid == 0) {
        __threadfence();
        unsigned t = atomicAdd(&g_ticket, 1u);
        s_last = (t == N - 1) ? 1 : 0;
    }
    __syncthreads();

    if (s_last) {
        if (tid == 0) g_ticket = 0;      // reset for next replay
        __threadfence();                  // acquire: see all g_asum/g_acnt

        float* rs = dr;                   // reuse smem
        int*   rc = (int*)pd;
        float s = 0.0f;
        int   c = 0;
        for (int i = tid; i < N; i += 256) {  // fixed order -> deterministic
            s += g_asum[i];
            c += g_acnt[i];
        }
        rs[tid] = s;
        rc[tid] = c;
        __syncthreads();
#pragma unroll
        for (int st = 128; st > 0; st >>= 1) {
            if (tid < st) { rs[tid] += rs[tid + st]; rc[tid] += rc[tid + st]; }
            __syncthreads();
        }
        if (tid == 0) {
            out[0] = rs[0] / ((float)rc[0] + 1e-16f);
        }
    }
}

// ---------------------------------------------------------------------------
extern "C" void kernel_launch(void* const* d_in, const int* in_sizes, int n_in,
                              void* d_out, int out_size) {
    const float* X      = (const float*)d_in[0];
    const int*   labels = (const int*)d_in[1];
    float*       out    = (float*)d_out;

    gram_sq_kernel<<<KSLICES * 36 + 96, 256>>>(X);
    triplet_kernel<<<N, 256>>>(labels, out);
}